// round 15
// baseline (speedup 1.0000x reference)
#include <cuda_runtime.h>
#include <cuda_bf16.h>
#include <cstdint>

// MolecularGraphNeuralNetwork — v12 = v10b (14.8us) + warp-local norms.
//
// 256 CTAs x 128 threads, 1 molecule/CTA (the proven 8-warps/SM shape).
// MLP : D1[32,64] = V@W^T, 3-term bf16 split, warp quadrant (16 atoms x
//       32 dims) exactly as round-10/13 verified.
// Prop: D2 = (A+I)@H DUPLICATED across the wn pair: each warp computes its
//       16 rows x all 64 dims (nt=8, K=32, 2-term). Buys warp-local L2
//       norms -> the ssP cross-warp round-trip and its barrier vanish:
//       2 barriers/layer instead of 3. V writes dedup'd by wn.
// Mol : molecular sum straight from fragments (shfl xor 4/8/16 over g4);
//       the vP array, its LDS sweep and a tail barrier are gone.

#define T_ATOMS 8192
#define B_MOL   256
#define APM     32
#define DIM     64
#define LH      3
#define BFP     72   // V/W bf16 rows: 144 B
#define HTP     40   // hT/A bf16 rows: 80 B

struct SmemLayout {
    float sBias[LH * DIM];
    float molP[2][DIM];             // per-wm-half molecule partials
    float molA[DIM];
    float molB[DIM];
    __nv_bfloat16 hThi[DIM][HTP];   // hT[d][j] = h[j][d], hi part
    __nv_bfloat16 hTlo[DIM][HTP];
    __nv_bfloat16 Abf[APM][HTP];    // (A+I), exact bf16
    __nv_bfloat16 Vhi[APM][BFP];
    __nv_bfloat16 Vlo[APM][BFP];
    __nv_bfloat16 Whi[DIM][BFP];
    __nv_bfloat16 Wlo[DIM][BFP];
};

#define MMA_BF16(d0,d1,d2,d3,a0,a1,a2,a3,b0,b1)                          \
    asm volatile("mma.sync.aligned.m16n8k16.row.col.f32.bf16.bf16.f32 "  \
        "{%0,%1,%2,%3}, {%4,%5,%6,%7}, {%8,%9}, {%0,%1,%2,%3};"          \
        : "+f"(d0), "+f"(d1), "+f"(d2), "+f"(d3)                          \
        : "r"(a0), "r"(a1), "r"(a2), "r"(a3), "r"(b0), "r"(b1))

__device__ __forceinline__ uint32_t lds_u32(const __nv_bfloat16* base, int byteOff) {
    return *reinterpret_cast<const uint32_t*>(
        reinterpret_cast<const char*>(base) + byteOff);
}

__global__ __launch_bounds__(128)
void gnn_mol_kernel(const int*   __restrict__ fp,
                    const float* __restrict__ adj,
                    const float* __restrict__ embed,
                    const float* __restrict__ W_fp,
                    const float* __restrict__ b_fp,
                    const float* __restrict__ W_out,
                    const float* __restrict__ b_out,
                    const float* __restrict__ W_prop,
                    const float* __restrict__ b_prop,
                    float*       __restrict__ out)
{
    extern __shared__ char smem_raw[];
    SmemLayout& S = *reinterpret_cast<SmemLayout*>(smem_raw);

    const int m    = blockIdx.x;
    const int tid  = threadIdx.x;
    const int lane = tid & 31;
    const int g    = tid >> 5;
    const int g4   = lane >> 2;     // mma group id (0..7)
    const int tig  = lane & 3;      // thread-in-group (0..3)
    const int wm   = g & 1;         // atom-tile half (rows 16wm..+15)
    const int wn   = g >> 1;        // dim half (for MLP compute + V writes)
    const int r0   = 16 * wm + g4;  // mma output rows (atoms)
    const int r1   = r0 + 8;
    const int i0   = g * 8;         // init-gather ownership only

    // ================= init =================
    if (tid < LH * DIM) S.sBias[tid] = b_fp[tid];
    if (tid + 128 < LH * DIM) S.sBias[tid + 128] = b_fp[tid + 128];

    // (A+I) -> exact bf16
    #pragma unroll
    for (int t = 0; t < 8; t++) {
        const int e = tid + t * 128;
        const int r = e >> 5, c = e & 31;
        const float a = adj[(size_t)(m * APM + r) * T_ATOMS + (size_t)m * APM + c];
        S.Abf[r][c] = __float2bfloat16(a + ((r == c) ? 1.0f : 0.0f));
    }
    // layer-0 weights -> bf16 hi/lo (bf16x2 packed stores)
    {
        const float2* W2 = reinterpret_cast<const float2*>(W_fp);
        #pragma unroll
        for (int t = 0; t < 16; t++) {
            const int e = tid + t * 128;
            const int d = e >> 5, c2 = e & 31;
            const float2 wv = W2[e];
            const __nv_bfloat162 hi = __floats2bfloat162_rn(wv.x, wv.y);
            const __nv_bfloat162 lo =
                __floats2bfloat162_rn(wv.x - __bfloat162float(hi.x),
                                      wv.y - __bfloat162float(hi.y));
            *reinterpret_cast<__nv_bfloat162*>(&S.Whi[d][2 * c2]) = hi;
            *reinterpret_cast<__nv_bfloat162*>(&S.Wlo[d][2 * c2]) = lo;
        }
    }
    // embedding gather -> bf16 hi/lo V
    #pragma unroll
    for (int q = 0; q < 8; q++) {
        const int atom = i0 + q;
        const int f = fp[m * APM + atom];
        const float x = embed[(size_t)f * DIM + lane];
        const float y = embed[(size_t)f * DIM + lane + 32];
        const __nv_bfloat16 xh = __float2bfloat16(x);
        const __nv_bfloat16 yh = __float2bfloat16(y);
        S.Vhi[atom][lane]      = xh;
        S.Vhi[atom][lane + 32] = yh;
        S.Vlo[atom][lane]      = __float2bfloat16(x - __bfloat162float(xh));
        S.Vlo[atom][lane + 32] = __float2bfloat16(y - __bfloat162float(yh));
    }
    __syncthreads();

    // prop A-fragments (rows r0/r1, K=32): loaded once, reused all layers
    uint32_t pa[2][4];
    #pragma unroll
    for (int kt = 0; kt < 2; kt++) {
        const int b0 = r0 * 80 + kt * 32 + tig * 4;
        pa[kt][0] = lds_u32(&S.Abf[0][0], b0);
        pa[kt][1] = lds_u32(&S.Abf[0][0], b0 + 8 * 80);
        pa[kt][2] = lds_u32(&S.Abf[0][0], b0 + 16);
        pa[kt][3] = lds_u32(&S.Abf[0][0], b0 + 8 * 80 + 16);
    }

    // ================= 3 GNN layers =================
    for (int l = 0; l < LH; l++) {
        // ---- MLP MMA (round-10-verified quadrant path) ---------------------
        uint32_t Ah[4][4], Al[4][4];
        #pragma unroll
        for (int kt = 0; kt < 4; kt++) {
            const int b0 = r0 * 144 + kt * 32 + tig * 4;
            Ah[kt][0] = lds_u32(&S.Vhi[0][0], b0);
            Ah[kt][1] = lds_u32(&S.Vhi[0][0], b0 + 8 * 144);
            Ah[kt][2] = lds_u32(&S.Vhi[0][0], b0 + 16);
            Ah[kt][3] = lds_u32(&S.Vhi[0][0], b0 + 8 * 144 + 16);
            Al[kt][0] = lds_u32(&S.Vlo[0][0], b0);
            Al[kt][1] = lds_u32(&S.Vlo[0][0], b0 + 8 * 144);
            Al[kt][2] = lds_u32(&S.Vlo[0][0], b0 + 16);
            Al[kt][3] = lds_u32(&S.Vlo[0][0], b0 + 8 * 144 + 16);
        }
        #pragma unroll
        for (int nt = 0; nt < 4; nt++) {
            float d0 = 0.f, d1 = 0.f, d2 = 0.f, d3 = 0.f;
            #pragma unroll
            for (int kt = 0; kt < 4; kt++) {
                const int rb = (32 * wn + nt * 8 + g4) * 144 + kt * 32 + tig * 4;
                const uint32_t bh0 = lds_u32(&S.Whi[0][0], rb);
                const uint32_t bh1 = lds_u32(&S.Whi[0][0], rb + 16);
                const uint32_t bl0 = lds_u32(&S.Wlo[0][0], rb);
                const uint32_t bl1 = lds_u32(&S.Wlo[0][0], rb + 16);
                MMA_BF16(d0, d1, d2, d3, Ah[kt][0], Ah[kt][1], Ah[kt][2], Ah[kt][3], bh0, bh1);
                MMA_BF16(d0, d1, d2, d3, Al[kt][0], Al[kt][1], Al[kt][2], Al[kt][3], bh0, bh1);
                MMA_BF16(d0, d1, d2, d3, Ah[kt][0], Ah[kt][1], Ah[kt][2], Ah[kt][3], bl0, bl1);
            }
            // bias + relu -> hi/lo transposed tiles hT[d][atom]
            const int c0 = 32 * wn + nt * 8 + 2 * tig;
            const float h00 = fmaxf(d0 + S.sBias[l * DIM + c0], 0.0f);
            const float h01 = fmaxf(d1 + S.sBias[l * DIM + c0 + 1], 0.0f);
            const float h10 = fmaxf(d2 + S.sBias[l * DIM + c0], 0.0f);
            const float h11 = fmaxf(d3 + S.sBias[l * DIM + c0 + 1], 0.0f);
            const __nv_bfloat16 a0 = __float2bfloat16(h00);
            const __nv_bfloat16 a1 = __float2bfloat16(h01);
            const __nv_bfloat16 a2 = __float2bfloat16(h10);
            const __nv_bfloat16 a3 = __float2bfloat16(h11);
            S.hThi[c0][r0]     = a0;
            S.hThi[c0 + 1][r0] = a1;
            S.hThi[c0][r1]     = a2;
            S.hThi[c0 + 1][r1] = a3;
            S.hTlo[c0][r0]     = __float2bfloat16(h00 - __bfloat162float(a0));
            S.hTlo[c0 + 1][r0] = __float2bfloat16(h01 - __bfloat162float(a1));
            S.hTlo[c0][r1]     = __float2bfloat16(h10 - __bfloat162float(a2));
            S.hTlo[c0 + 1][r1] = __float2bfloat16(h11 - __bfloat162float(a3));
        }
        __syncthreads();   // hT published; all V/W fragment reads complete

        // prefetch next layer's weights (Whi/Wlo idle until after next barrier)
        if (l + 1 < LH) {
            const float2* Wn2 =
                reinterpret_cast<const float2*>(W_fp + (l + 1) * DIM * DIM);
            #pragma unroll
            for (int t = 0; t < 16; t++) {
                const int e = tid + t * 128;
                const int d = e >> 5, c2 = e & 31;
                const float2 wv = Wn2[e];
                const __nv_bfloat162 hi = __floats2bfloat162_rn(wv.x, wv.y);
                const __nv_bfloat162 lo =
                    __floats2bfloat162_rn(wv.x - __bfloat162float(hi.x),
                                          wv.y - __bfloat162float(hi.y));
                *reinterpret_cast<__nv_bfloat162*>(&S.Whi[d][2 * c2]) = hi;
                *reinterpret_cast<__nv_bfloat162*>(&S.Wlo[d][2 * c2]) = lo;
            }
        }

        // ---- prop MMA, DUPLICATED across wn: 16 rows x all 64 dims --------
        float dr[8][4];
        #pragma unroll
        for (int nt = 0; nt < 8; nt++) {
            float d0 = 0.f, d1 = 0.f, d2 = 0.f, d3 = 0.f;
            #pragma unroll
            for (int kt = 0; kt < 2; kt++) {
                const int rb = (nt * 8 + g4) * 80 + kt * 32 + tig * 4;
                const uint32_t bh0 = lds_u32(&S.hThi[0][0], rb);
                const uint32_t bh1 = lds_u32(&S.hThi[0][0], rb + 16);
                const uint32_t bl0 = lds_u32(&S.hTlo[0][0], rb);
                const uint32_t bl1 = lds_u32(&S.hTlo[0][0], rb + 16);
                MMA_BF16(d0, d1, d2, d3, pa[kt][0], pa[kt][1], pa[kt][2], pa[kt][3], bh0, bh1);
                MMA_BF16(d0, d1, d2, d3, pa[kt][0], pa[kt][1], pa[kt][2], pa[kt][3], bl0, bl1);
            }
            dr[nt][0] = d0; dr[nt][1] = d1; dr[nt][2] = d2; dr[nt][3] = d3;
        }

        // ---- warp-local L2 norms (all 64 dims inside this warp) -----------
        float ss0 = 0.f, ss1 = 0.f;
        #pragma unroll
        for (int nt = 0; nt < 8; nt++) {
            ss0 = fmaf(dr[nt][0], dr[nt][0], fmaf(dr[nt][1], dr[nt][1], ss0));
            ss1 = fmaf(dr[nt][2], dr[nt][2], fmaf(dr[nt][3], dr[nt][3], ss1));
        }
        ss0 += __shfl_xor_sync(0xffffffffu, ss0, 1);
        ss0 += __shfl_xor_sync(0xffffffffu, ss0, 2);
        ss1 += __shfl_xor_sync(0xffffffffu, ss1, 1);
        ss1 += __shfl_xor_sync(0xffffffffu, ss1, 2);
        const float inv0 = rsqrtf(fmaxf(ss0, 1e-24f));   // 1/max(||.||,1e-12)
        const float inv1 = rsqrtf(fmaxf(ss1, 1e-24f));

        if (l < LH - 1) {
            // normalized v -> Vhi/Vlo; warp writes ONLY its wn dim-half
            #pragma unroll
            for (int q = 0; q < 4; q++) {
                const int nt = 4 * wn + q;
                const int c0 = nt * 8 + 2 * tig;
                const float v00 = dr[nt][0] * inv0, v01 = dr[nt][1] * inv0;
                const float v10 = dr[nt][2] * inv1, v11 = dr[nt][3] * inv1;
                const __nv_bfloat162 hiA = __floats2bfloat162_rn(v00, v01);
                const __nv_bfloat162 hiB = __floats2bfloat162_rn(v10, v11);
                const __nv_bfloat162 loA =
                    __floats2bfloat162_rn(v00 - __bfloat162float(hiA.x),
                                          v01 - __bfloat162float(hiA.y));
                const __nv_bfloat162 loB =
                    __floats2bfloat162_rn(v10 - __bfloat162float(hiB.x),
                                          v11 - __bfloat162float(hiB.y));
                *reinterpret_cast<__nv_bfloat162*>(&S.Vhi[r0][c0]) = hiA;
                *reinterpret_cast<__nv_bfloat162*>(&S.Vhi[r1][c0]) = hiB;
                *reinterpret_cast<__nv_bfloat162*>(&S.Vlo[r0][c0]) = loA;
                *reinterpret_cast<__nv_bfloat162*>(&S.Vlo[r1][c0]) = loB;
            }
            __syncthreads();   // V published; hT free; W prefetch visible
        } else {
            // ---- molecular sum from fragments (16 atoms per wm half) ------
            float colsum[8][2];
            #pragma unroll
            for (int nt = 0; nt < 8; nt++) {
                colsum[nt][0] = dr[nt][0] * inv0 + dr[nt][2] * inv1;
                colsum[nt][1] = dr[nt][1] * inv0 + dr[nt][3] * inv1;
            }
            #pragma unroll
            for (int nt = 0; nt < 8; nt++) {
                #pragma unroll
                for (int h = 0; h < 2; h++) {
                    float v = colsum[nt][h];
                    v += __shfl_xor_sync(0xffffffffu, v, 4);
                    v += __shfl_xor_sync(0xffffffffu, v, 8);
                    v += __shfl_xor_sync(0xffffffffu, v, 16);
                    colsum[nt][h] = v;
                }
            }
            if (wn == 0 && g4 == 0) {     // one warp per wm half writes
                #pragma unroll
                for (int nt = 0; nt < 8; nt++) {
                    const int c0 = nt * 8 + 2 * tig;
                    S.molP[wm][c0]     = colsum[nt][0];
                    S.molP[wm][c0 + 1] = colsum[nt][1];
                }
            }
            __syncthreads();
        }
    }

    // ================= output MLP =================
    if (tid < DIM) {
        S.molA[tid] = S.molP[0][tid] + S.molP[1][tid];
    }
    __syncthreads();
    if (tid < DIM) {
        const float* Wr = W_out + tid * DIM;
        float a = b_out[tid];
        #pragma unroll
        for (int k = 0; k < DIM; k += 4) {
            const float4 w4 = *reinterpret_cast<const float4*>(&Wr[k]);
            a += S.molA[k] * w4.x + S.molA[k + 1] * w4.y
               + S.molA[k + 2] * w4.z + S.molA[k + 3] * w4.w;
        }
        S.molB[tid] = fmaxf(a, 0.0f);
    }
    __syncthreads();
    if (tid < DIM) {
        const float* Wr = W_out + DIM * DIM + tid * DIM;
        float a = b_out[DIM + tid];
        #pragma unroll
        for (int k = 0; k < DIM; k += 4) {
            const float4 w4 = *reinterpret_cast<const float4*>(&Wr[k]);
            a += S.molB[k] * w4.x + S.molB[k + 1] * w4.y
               + S.molB[k + 2] * w4.z + S.molB[k + 3] * w4.w;
        }
        S.molA[tid] = fmaxf(a, 0.0f);
    }
    __syncthreads();

    // ================= final property =================
    if (g == 0) {
        float s = S.molA[lane] * W_prop[lane]
                + S.molA[lane + 32] * W_prop[lane + 32];
        #pragma unroll
        for (int o = 16; o; o >>= 1)
            s += __shfl_xor_sync(0xffffffffu, s, o);
        if (lane == 0) out[m] = s + b_prop[0];
    }
}

extern "C" void kernel_launch(void* const* d_in, const int* in_sizes, int n_in,
                              void* d_out, int out_size)
{
    // metadata order: fingerprints, adjacency, segment_ids, embed,
    //                 W_fp, b_fp, W_out, b_out, W_prop, b_prop
    const int*   fp     = (const int*)  d_in[0];
    const float* adj    = (const float*)d_in[1];
    // d_in[2] = segment_ids: repeat(arange(256), 32), used implicitly
    const float* embed  = (const float*)d_in[3];
    const float* W_fp   = (const float*)d_in[4];
    const float* b_fp   = (const float*)d_in[5];
    const float* W_out  = (const float*)d_in[6];
    const float* b_out  = (const float*)d_in[7];
    const float* W_prop = (const float*)d_in[8];
    const float* b_prop = (const float*)d_in[9];
    float* outp = (float*)d_out;

    const int smem_bytes = (int)sizeof(SmemLayout);   // ~42 KB
    cudaFuncSetAttribute(gnn_mol_kernel,
                         cudaFuncAttributeMaxDynamicSharedMemorySize, smem_bytes);

    gnn_mol_kernel<<<B_MOL, 128, smem_bytes>>>(fp, adj, embed, W_fp, b_fp,
                                               W_out, b_out, W_prop, b_prop,
                                               outp);
}

// round 16
// speedup vs baseline: 1.1429x; 1.1429x over previous
#include <cuda_runtime.h>
#include <cuda_bf16.h>
#include <cstdint>

// MolecularGraphNeuralNetwork — v13 = v10b (14.8us) + deferred normalization.
//
// 256 CTAs x 128 threads, 1 molecule/CTA (the proven 8-warps/SM shape).
// Row scaling commutes with GEMM: relu((inv*v)@W^T+b) = relu(inv*(v@W^T)+b).
// So epilogue 2 stores V UNNORMALIZED + ss-partials behind ONE barrier, and
// the next MLP epilogue applies inv_r (2 MUFU/thread, hidden under MMAs).
// 2 barriers/layer instead of 3, with zero added per-warp chain length
// (the v11/v12 mistake). Layer 0 reads ssP pre-initialized to {1,0}.
// Tail: mol-sum from fragments (v12-verified shfl path); vP array deleted.

#define T_ATOMS 8192
#define B_MOL   256
#define APM     32
#define DIM     64
#define LH      3
#define BFP     72   // V/W bf16 rows: 144 B
#define HTP     40   // hT/A bf16 rows: 80 B

struct SmemLayout {
    float sBias[LH * DIM];
    float ssP[2][APM];              // per-wn partial sum-of-squares
    float molP[2][DIM];             // per-wm-half molecule partials
    float molA[DIM];
    float molB[DIM];
    __nv_bfloat16 hThi[DIM][HTP];   // hT[d][j] = h[j][d], hi part
    __nv_bfloat16 hTlo[DIM][HTP];
    __nv_bfloat16 Abf[APM][HTP];    // (A+I), exact bf16
    __nv_bfloat16 Vhi[APM][BFP];    // UNNORMALIZED after layer epilogues
    __nv_bfloat16 Vlo[APM][BFP];
    __nv_bfloat16 Whi[DIM][BFP];
    __nv_bfloat16 Wlo[DIM][BFP];
};

#define MMA_BF16(d0,d1,d2,d3,a0,a1,a2,a3,b0,b1)                          \
    asm volatile("mma.sync.aligned.m16n8k16.row.col.f32.bf16.bf16.f32 "  \
        "{%0,%1,%2,%3}, {%4,%5,%6,%7}, {%8,%9}, {%0,%1,%2,%3};"          \
        : "+f"(d0), "+f"(d1), "+f"(d2), "+f"(d3)                          \
        : "r"(a0), "r"(a1), "r"(a2), "r"(a3), "r"(b0), "r"(b1))

__device__ __forceinline__ uint32_t lds_u32(const __nv_bfloat16* base, int byteOff) {
    return *reinterpret_cast<const uint32_t*>(
        reinterpret_cast<const char*>(base) + byteOff);
}

__global__ __launch_bounds__(128)
void gnn_mol_kernel(const int*   __restrict__ fp,
                    const float* __restrict__ adj,
                    const float* __restrict__ embed,
                    const float* __restrict__ W_fp,
                    const float* __restrict__ b_fp,
                    const float* __restrict__ W_out,
                    const float* __restrict__ b_out,
                    const float* __restrict__ W_prop,
                    const float* __restrict__ b_prop,
                    float*       __restrict__ out)
{
    extern __shared__ char smem_raw[];
    SmemLayout& S = *reinterpret_cast<SmemLayout*>(smem_raw);

    const int m    = blockIdx.x;
    const int tid  = threadIdx.x;
    const int lane = tid & 31;
    const int g    = tid >> 5;
    const int g4   = lane >> 2;     // mma group id (0..7)
    const int tig  = lane & 3;      // thread-in-group (0..3)
    const int wm   = g & 1;         // atom-tile half (rows 16wm..+15)
    const int wn   = g >> 1;        // dim half (dims 32wn..+31)
    const int r0   = 16 * wm + g4;  // mma output rows (atoms)
    const int r1   = r0 + 8;
    const int i0   = g * 8;         // init-gather ownership only

    // ================= init =================
    if (tid < LH * DIM) S.sBias[tid] = b_fp[tid];
    if (tid + 128 < LH * DIM) S.sBias[tid + 128] = b_fp[tid + 128];
    // ssP starts as {1,0}: layer-0 MLP epilogue then applies inv = 1 exactly
    if (tid < APM) { S.ssP[0][tid] = 1.0f; S.ssP[1][tid] = 0.0f; }

    // (A+I) -> exact bf16
    #pragma unroll
    for (int t = 0; t < 8; t++) {
        const int e = tid + t * 128;
        const int r = e >> 5, c = e & 31;
        const float a = adj[(size_t)(m * APM + r) * T_ATOMS + (size_t)m * APM + c];
        S.Abf[r][c] = __float2bfloat16(a + ((r == c) ? 1.0f : 0.0f));
    }
    // layer-0 weights -> bf16 hi/lo (bf16x2 packed stores)
    {
        const float2* W2 = reinterpret_cast<const float2*>(W_fp);
        #pragma unroll
        for (int t = 0; t < 16; t++) {
            const int e = tid + t * 128;
            const int d = e >> 5, c2 = e & 31;
            const float2 wv = W2[e];
            const __nv_bfloat162 hi = __floats2bfloat162_rn(wv.x, wv.y);
            const __nv_bfloat162 lo =
                __floats2bfloat162_rn(wv.x - __bfloat162float(hi.x),
                                      wv.y - __bfloat162float(hi.y));
            *reinterpret_cast<__nv_bfloat162*>(&S.Whi[d][2 * c2]) = hi;
            *reinterpret_cast<__nv_bfloat162*>(&S.Wlo[d][2 * c2]) = lo;
        }
    }
    // embedding gather -> bf16 hi/lo V
    #pragma unroll
    for (int q = 0; q < 8; q++) {
        const int atom = i0 + q;
        const int f = fp[m * APM + atom];
        const float x = embed[(size_t)f * DIM + lane];
        const float y = embed[(size_t)f * DIM + lane + 32];
        const __nv_bfloat16 xh = __float2bfloat16(x);
        const __nv_bfloat16 yh = __float2bfloat16(y);
        S.Vhi[atom][lane]      = xh;
        S.Vhi[atom][lane + 32] = yh;
        S.Vlo[atom][lane]      = __float2bfloat16(x - __bfloat162float(xh));
        S.Vlo[atom][lane + 32] = __float2bfloat16(y - __bfloat162float(yh));
    }
    __syncthreads();

    // prop A-fragments (rows r0/r1, K=32): loaded once, reused all layers
    uint32_t pa[2][4];
    #pragma unroll
    for (int kt = 0; kt < 2; kt++) {
        const int b0 = r0 * 80 + kt * 32 + tig * 4;
        pa[kt][0] = lds_u32(&S.Abf[0][0], b0);
        pa[kt][1] = lds_u32(&S.Abf[0][0], b0 + 8 * 80);
        pa[kt][2] = lds_u32(&S.Abf[0][0], b0 + 16);
        pa[kt][3] = lds_u32(&S.Abf[0][0], b0 + 8 * 80 + 16);
    }

    // ================= 3 GNN layers =================
    for (int l = 0; l < LH; l++) {
        // deferred inv for this thread's 2 atom rows (layer 0: ssP={1,0} -> 1)
        const float inv0 = rsqrtf(fmaxf(S.ssP[0][r0] + S.ssP[1][r0], 1e-24f));
        const float inv1 = rsqrtf(fmaxf(S.ssP[0][r1] + S.ssP[1][r1], 1e-24f));

        // ---- MLP MMA (round-10-verified quadrant path) ---------------------
        uint32_t Ah[4][4], Al[4][4];
        #pragma unroll
        for (int kt = 0; kt < 4; kt++) {
            const int b0 = r0 * 144 + kt * 32 + tig * 4;
            Ah[kt][0] = lds_u32(&S.Vhi[0][0], b0);
            Ah[kt][1] = lds_u32(&S.Vhi[0][0], b0 + 8 * 144);
            Ah[kt][2] = lds_u32(&S.Vhi[0][0], b0 + 16);
            Ah[kt][3] = lds_u32(&S.Vhi[0][0], b0 + 8 * 144 + 16);
            Al[kt][0] = lds_u32(&S.Vlo[0][0], b0);
            Al[kt][1] = lds_u32(&S.Vlo[0][0], b0 + 8 * 144);
            Al[kt][2] = lds_u32(&S.Vlo[0][0], b0 + 16);
            Al[kt][3] = lds_u32(&S.Vlo[0][0], b0 + 8 * 144 + 16);
        }
        #pragma unroll
        for (int nt = 0; nt < 4; nt++) {
            float d0 = 0.f, d1 = 0.f, d2 = 0.f, d3 = 0.f;
            #pragma unroll
            for (int kt = 0; kt < 4; kt++) {
                const int rb = (32 * wn + nt * 8 + g4) * 144 + kt * 32 + tig * 4;
                const uint32_t bh0 = lds_u32(&S.Whi[0][0], rb);
                const uint32_t bh1 = lds_u32(&S.Whi[0][0], rb + 16);
                const uint32_t bl0 = lds_u32(&S.Wlo[0][0], rb);
                const uint32_t bl1 = lds_u32(&S.Wlo[0][0], rb + 16);
                MMA_BF16(d0, d1, d2, d3, Ah[kt][0], Ah[kt][1], Ah[kt][2], Ah[kt][3], bh0, bh1);
                MMA_BF16(d0, d1, d2, d3, Al[kt][0], Al[kt][1], Al[kt][2], Al[kt][3], bh0, bh1);
                MMA_BF16(d0, d1, d2, d3, Ah[kt][0], Ah[kt][1], Ah[kt][2], Ah[kt][3], bl0, bl1);
            }
            // deferred-inv scale + bias + relu -> hi/lo tiles hT[d][atom]
            const int c0 = 32 * wn + nt * 8 + 2 * tig;
            const float h00 = fmaxf(d0 * inv0 + S.sBias[l * DIM + c0], 0.0f);
            const float h01 = fmaxf(d1 * inv0 + S.sBias[l * DIM + c0 + 1], 0.0f);
            const float h10 = fmaxf(d2 * inv1 + S.sBias[l * DIM + c0], 0.0f);
            const float h11 = fmaxf(d3 * inv1 + S.sBias[l * DIM + c0 + 1], 0.0f);
            const __nv_bfloat16 a0 = __float2bfloat16(h00);
            const __nv_bfloat16 a1 = __float2bfloat16(h01);
            const __nv_bfloat16 a2 = __float2bfloat16(h10);
            const __nv_bfloat16 a3 = __float2bfloat16(h11);
            S.hThi[c0][r0]     = a0;
            S.hThi[c0 + 1][r0] = a1;
            S.hThi[c0][r1]     = a2;
            S.hThi[c0 + 1][r1] = a3;
            S.hTlo[c0][r0]     = __float2bfloat16(h00 - __bfloat162float(a0));
            S.hTlo[c0 + 1][r0] = __float2bfloat16(h01 - __bfloat162float(a1));
            S.hTlo[c0][r1]     = __float2bfloat16(h10 - __bfloat162float(a2));
            S.hTlo[c0 + 1][r1] = __float2bfloat16(h11 - __bfloat162float(a3));
        }
        __syncthreads();   // hT published; V/W/ssP reads complete

        // prefetch next layer's weights (Whi/Wlo idle until after next barrier)
        if (l + 1 < LH) {
            const float2* Wn2 =
                reinterpret_cast<const float2*>(W_fp + (l + 1) * DIM * DIM);
            #pragma unroll
            for (int t = 0; t < 16; t++) {
                const int e = tid + t * 128;
                const int d = e >> 5, c2 = e & 31;
                const float2 wv = Wn2[e];
                const __nv_bfloat162 hi = __floats2bfloat162_rn(wv.x, wv.y);
                const __nv_bfloat162 lo =
                    __floats2bfloat162_rn(wv.x - __bfloat162float(hi.x),
                                          wv.y - __bfloat162float(hi.y));
                *reinterpret_cast<__nv_bfloat162*>(&S.Whi[d][2 * c2]) = hi;
                *reinterpret_cast<__nv_bfloat162*>(&S.Wlo[d][2 * c2]) = lo;
            }
        }

        // ---- prop MMA: D2 = (A+I) @ (Hhi + Hlo), 4 n-tiles (own wn half) ---
        float dr[4][4];
        #pragma unroll
        for (int nt = 0; nt < 4; nt++) {
            float d0 = 0.f, d1 = 0.f, d2 = 0.f, d3 = 0.f;
            #pragma unroll
            for (int kt = 0; kt < 2; kt++) {
                const int rb = (32 * wn + nt * 8 + g4) * 80 + kt * 32 + tig * 4;
                const uint32_t bh0 = lds_u32(&S.hThi[0][0], rb);
                const uint32_t bh1 = lds_u32(&S.hThi[0][0], rb + 16);
                const uint32_t bl0 = lds_u32(&S.hTlo[0][0], rb);
                const uint32_t bl1 = lds_u32(&S.hTlo[0][0], rb + 16);
                MMA_BF16(d0, d1, d2, d3, pa[kt][0], pa[kt][1], pa[kt][2], pa[kt][3], bh0, bh1);
                MMA_BF16(d0, d1, d2, d3, pa[kt][0], pa[kt][1], pa[kt][2], pa[kt][3], bl0, bl1);
            }
            dr[nt][0] = d0; dr[nt][1] = d1; dr[nt][2] = d2; dr[nt][3] = d3;
        }

        // ---- ss partials (this warp's 32 dims of rows r0/r1) ---------------
        float ss0 = 0.f, ss1 = 0.f;
        #pragma unroll
        for (int nt = 0; nt < 4; nt++) {
            ss0 = fmaf(dr[nt][0], dr[nt][0], fmaf(dr[nt][1], dr[nt][1], ss0));
            ss1 = fmaf(dr[nt][2], dr[nt][2], fmaf(dr[nt][3], dr[nt][3], ss1));
        }
        ss0 += __shfl_xor_sync(0xffffffffu, ss0, 1);
        ss0 += __shfl_xor_sync(0xffffffffu, ss0, 2);
        ss1 += __shfl_xor_sync(0xffffffffu, ss1, 1);
        ss1 += __shfl_xor_sync(0xffffffffu, ss1, 2);
        if (tig == 0) {
            S.ssP[wn][r0] = ss0;
            S.ssP[wn][r1] = ss1;
        }

        if (l < LH - 1) {
            // store V UNNORMALIZED (deferred inv); one barrier covers V + ssP
            #pragma unroll
            for (int nt = 0; nt < 4; nt++) {
                const int c0 = 32 * wn + nt * 8 + 2 * tig;
                const __nv_bfloat162 hiA = __floats2bfloat162_rn(dr[nt][0], dr[nt][1]);
                const __nv_bfloat162 hiB = __floats2bfloat162_rn(dr[nt][2], dr[nt][3]);
                const __nv_bfloat162 loA =
                    __floats2bfloat162_rn(dr[nt][0] - __bfloat162float(hiA.x),
                                          dr[nt][1] - __bfloat162float(hiA.y));
                const __nv_bfloat162 loB =
                    __floats2bfloat162_rn(dr[nt][2] - __bfloat162float(hiB.x),
                                          dr[nt][3] - __bfloat162float(hiB.y));
                *reinterpret_cast<__nv_bfloat162*>(&S.Vhi[r0][c0]) = hiA;
                *reinterpret_cast<__nv_bfloat162*>(&S.Vhi[r1][c0]) = hiB;
                *reinterpret_cast<__nv_bfloat162*>(&S.Vlo[r0][c0]) = loA;
                *reinterpret_cast<__nv_bfloat162*>(&S.Vlo[r1][c0]) = loB;
            }
            __syncthreads();   // V + ssP published; hT free; W prefetch visible
        } else {
            // ---- tail: exchange ssP, then mol-sum from fragments ----------
            __syncthreads();   // ssP published
            const float fin0 = rsqrtf(fmaxf(S.ssP[0][r0] + S.ssP[1][r0], 1e-24f));
            const float fin1 = rsqrtf(fmaxf(S.ssP[0][r1] + S.ssP[1][r1], 1e-24f));
            float colsum[4][2];
            #pragma unroll
            for (int nt = 0; nt < 4; nt++) {
                colsum[nt][0] = dr[nt][0] * fin0 + dr[nt][2] * fin1;
                colsum[nt][1] = dr[nt][1] * fin0 + dr[nt][3] * fin1;
            }
            #pragma unroll
            for (int nt = 0; nt < 4; nt++) {
                #pragma unroll
                for (int h = 0; h < 2; h++) {
                    float v = colsum[nt][h];
                    v += __shfl_xor_sync(0xffffffffu, v, 4);
                    v += __shfl_xor_sync(0xffffffffu, v, 8);
                    v += __shfl_xor_sync(0xffffffffu, v, 16);
                    colsum[nt][h] = v;
                }
            }
            if (g4 == 0) {     // each (wm, wn) warp writes its own 8 cols
                #pragma unroll
                for (int nt = 0; nt < 4; nt++) {
                    const int c0 = 32 * wn + nt * 8 + 2 * tig;
                    S.molP[wm][c0]     = colsum[nt][0];
                    S.molP[wm][c0 + 1] = colsum[nt][1];
                }
            }
            __syncthreads();
        }
    }

    // ================= output MLP =================
    if (tid < DIM) {
        S.molA[tid] = S.molP[0][tid] + S.molP[1][tid];
    }
    __syncthreads();
    if (tid < DIM) {
        const float* Wr = W_out + tid * DIM;
        float a = b_out[tid];
        #pragma unroll
        for (int k = 0; k < DIM; k += 4) {
            const float4 w4 = *reinterpret_cast<const float4*>(&Wr[k]);
            a += S.molA[k] * w4.x + S.molA[k + 1] * w4.y
               + S.molA[k + 2] * w4.z + S.molA[k + 3] * w4.w;
        }
        S.molB[tid] = fmaxf(a, 0.0f);
    }
    __syncthreads();
    if (tid < DIM) {
        const float* Wr = W_out + DIM * DIM + tid * DIM;
        float a = b_out[DIM + tid];
        #pragma unroll
        for (int k = 0; k < DIM; k += 4) {
            const float4 w4 = *reinterpret_cast<const float4*>(&Wr[k]);
            a += S.molB[k] * w4.x + S.molB[k + 1] * w4.y
               + S.molB[k + 2] * w4.z + S.molB[k + 3] * w4.w;
        }
        S.molA[tid] = fmaxf(a, 0.0f);
    }
    __syncthreads();

    // ================= final property =================
    if (g == 0) {
        float s = S.molA[lane] * W_prop[lane]
                + S.molA[lane + 32] * W_prop[lane + 32];
        #pragma unroll
        for (int o = 16; o; o >>= 1)
            s += __shfl_xor_sync(0xffffffffu, s, o);
        if (lane == 0) out[m] = s + b_prop[0];
    }
}

extern "C" void kernel_launch(void* const* d_in, const int* in_sizes, int n_in,
                              void* d_out, int out_size)
{
    // metadata order: fingerprints, adjacency, segment_ids, embed,
    //                 W_fp, b_fp, W_out, b_out, W_prop, b_prop
    const int*   fp     = (const int*)  d_in[0];
    const float* adj    = (const float*)d_in[1];
    // d_in[2] = segment_ids: repeat(arange(256), 32), used implicitly
    const float* embed  = (const float*)d_in[3];
    const float* W_fp   = (const float*)d_in[4];
    const float* b_fp   = (const float*)d_in[5];
    const float* W_out  = (const float*)d_in[6];
    const float* b_out  = (const float*)d_in[7];
    const float* W_prop = (const float*)d_in[8];
    const float* b_prop = (const float*)d_in[9];
    float* outp = (float*)d_out;

    const int smem_bytes = (int)sizeof(SmemLayout);   // ~43 KB
    cudaFuncSetAttribute(gnn_mol_kernel,
                         cudaFuncAttributeMaxDynamicSharedMemorySize, smem_bytes);

    gnn_mol_kernel<<<B_MOL, 128, smem_bytes>>>(fp, adj, embed, W_fp, b_fp,
                                               W_out, b_out, W_prop, b_prop,
                                               outp);
}